// round 14
// baseline (speedup 1.0000x reference)
#include <cuda_runtime.h>
#include <cuda_bf16.h>
#include <cstdint>

// out[i,j] = 2*x[i,j] + 5 - (i+j), x: [8192, 8192] fp32
// HBM-streaming kernel (~90% of spec BW). Flat launch, straight-line body:
// 8 independent float4 loads per thread (MLP=8), 512-thread blocks, 4096 CTAs.

static constexpr int N_COLS = 8192;
static constexpr int COLS4  = N_COLS / 4;                       // 2048 float4/row
static constexpr unsigned int TOTAL4 = 8192u * COLS4;           // 16,777,216
static constexpr unsigned int STRIDE = TOTAL4 / 8;              // 2,097,152
static constexpr unsigned int NTHR   = 512u;

__device__ __forceinline__ float4 ld_lu(const float4* p)
{
    float4 v;
    asm volatile("ld.global.lu.v4.f32 {%0,%1,%2,%3}, [%4];"
                 : "=f"(v.x), "=f"(v.y), "=f"(v.z), "=f"(v.w)
                 : "l"(p));
    return v;
}

__device__ __forceinline__ float4 compute(unsigned int idx, float4 v)
{
    unsigned int row  = idx >> 11;          // idx / 2048
    unsigned int col  = (idx & 2047u) << 2; // first scalar column of this float4
    float base = 5.0f - (float)(row + col);
    float4 o;
    o.x = fmaf(2.0f, v.x, base);
    o.y = fmaf(2.0f, v.y, base - 1.0f);
    o.z = fmaf(2.0f, v.z, base - 2.0f);
    o.w = fmaf(2.0f, v.w, base - 3.0f);
    return o;
}

__global__ __launch_bounds__(NTHR) void fused_map_kernel(
    const float4* __restrict__ in, float4* __restrict__ out)
{
    unsigned int t = blockIdx.x * NTHR + threadIdx.x;   // 0 .. STRIDE-1

    unsigned int idx[8];
    float4 v[8];
#pragma unroll
    for (int k = 0; k < 8; k++) idx[k] = t + (unsigned int)k * STRIDE;

    // Front-batched independent loads (MLP=8), last-use read policy.
#pragma unroll
    for (int k = 0; k < 8; k++) v[k] = ld_lu(in + idx[k]);

    // Evict-first stores: write-once data.
#pragma unroll
    for (int k = 0; k < 8; k++) __stcs(out + idx[k], compute(idx[k], v[k]));
}

extern "C" void kernel_launch(void* const* d_in, const int* in_sizes, int n_in,
                              void* d_out, int out_size)
{
    const float4* in  = (const float4*)d_in[0];
    float4*       out = (float4*)d_out;
    unsigned int blocks = STRIDE / NTHR;   // 4096 blocks
    fused_map_kernel<<<blocks, NTHR>>>(in, out);
}

// round 15
// speedup vs baseline: 1.0008x; 1.0008x over previous
#include <cuda_runtime.h>
#include <cuda_bf16.h>
#include <cstdint>

// out[i,j] = 2*x[i,j] + 5 - (i+j), x: [8192, 8192] fp32
// HBM-streaming kernel at ~90% of spec BW (7.2-7.3 TB/s). Flat launch,
// straight-line body: 4 independent float4 loads per thread (MLP=4),
// 512-thread blocks, 8192 CTAs. Non-coherent read path, evict-first stores.

static constexpr int N_COLS = 8192;
static constexpr int COLS4  = N_COLS / 4;                       // 2048 float4/row
static constexpr unsigned int TOTAL4 = 8192u * COLS4;           // 16,777,216
static constexpr unsigned int QUART4 = TOTAL4 / 4;              // 4,194,304
static constexpr unsigned int NTHR   = 512u;

__device__ __forceinline__ float4 ld_nc(const float4* p)
{
    float4 v;
    asm volatile("ld.global.nc.v4.f32 {%0,%1,%2,%3}, [%4];"
                 : "=f"(v.x), "=f"(v.y), "=f"(v.z), "=f"(v.w)
                 : "l"(p));
    return v;
}

__device__ __forceinline__ float4 compute(unsigned int idx, float4 v)
{
    unsigned int row  = idx >> 11;          // idx / 2048
    unsigned int col  = (idx & 2047u) << 2; // first scalar column of this float4
    float base = 5.0f - (float)(row + col);
    float4 o;
    o.x = fmaf(2.0f, v.x, base);
    o.y = fmaf(2.0f, v.y, base - 1.0f);
    o.z = fmaf(2.0f, v.z, base - 2.0f);
    o.w = fmaf(2.0f, v.w, base - 3.0f);
    return o;
}

__global__ __launch_bounds__(NTHR) void fused_map_kernel(
    const float4* __restrict__ in, float4* __restrict__ out)
{
    unsigned int t = blockIdx.x * NTHR + threadIdx.x;   // 0 .. QUART4-1
    unsigned int i0 = t;
    unsigned int i1 = t + QUART4;
    unsigned int i2 = t + 2u * QUART4;
    unsigned int i3 = t + 3u * QUART4;

    // Front-batched independent loads (MLP=4), non-coherent read path.
    float4 v0 = ld_nc(in + i0);
    float4 v1 = ld_nc(in + i1);
    float4 v2 = ld_nc(in + i2);
    float4 v3 = ld_nc(in + i3);

    // Evict-first stores: write-once data.
    __stcs(out + i0, compute(i0, v0));
    __stcs(out + i1, compute(i1, v1));
    __stcs(out + i2, compute(i2, v2));
    __stcs(out + i3, compute(i3, v3));
}

extern "C" void kernel_launch(void* const* d_in, const int* in_sizes, int n_in,
                              void* d_out, int out_size)
{
    const float4* in  = (const float4*)d_in[0];
    float4*       out = (float4*)d_out;
    unsigned int blocks = QUART4 / NTHR;   // 8192 blocks
    fused_map_kernel<<<blocks, NTHR>>>(in, out);
}